// round 7
// baseline (speedup 1.0000x reference)
#include <cuda_runtime.h>

// B=8, T=4096, D=2048, W=4
// y[b,t,d] = silu( sum_{k=0..3} w[k,d] * x[b, t-3+k, d] )  (zero-pad t<0)
//
// 256-bit-wide streaming kernel: each thread owns 8 channels (32B) and a
// TC=8 sliding window over t. v8.b32 global loads/stores (sm_100+) double
// bytes-in-flight per LSU issue vs float4.

#define B_DIM 8
#define T_DIM 4096
#define D_DIM 2048
#define D8    (D_DIM / 8)       // 256 float8 per row
#define TC    8                 // t-values per thread
#define NCH   (T_DIM / TC)      // 512 chunks per batch

struct __align__(32) f8 { float v[8]; };

__device__ __forceinline__ f8 ld8(const float* p) {
    f8 r;
    asm volatile("ld.global.v8.b32 {%0,%1,%2,%3,%4,%5,%6,%7}, [%8];"
                 : "=f"(r.v[0]), "=f"(r.v[1]), "=f"(r.v[2]), "=f"(r.v[3]),
                   "=f"(r.v[4]), "=f"(r.v[5]), "=f"(r.v[6]), "=f"(r.v[7])
                 : "l"(p));
    return r;
}

__device__ __forceinline__ void st8(float* p, const f8& r) {
    asm volatile("st.global.v8.b32 [%0], {%1,%2,%3,%4,%5,%6,%7,%8};"
                 :: "l"(p),
                    "f"(r.v[0]), "f"(r.v[1]), "f"(r.v[2]), "f"(r.v[3]),
                    "f"(r.v[4]), "f"(r.v[5]), "f"(r.v[6]), "f"(r.v[7])
                 : "memory");
}

// silu(v) = 0.5*v*(1 + tanh(0.5*v))  -> single MUFU.TANH
__device__ __forceinline__ float silu_f(float v) {
    float t;
    asm("tanh.approx.f32 %0, %1;" : "=f"(t) : "f"(0.5f * v));
    return fmaf(0.5f * v, t, 0.5f * v);
}

__global__ __launch_bounds__(256) void conv_silu_kernel(
    const float* __restrict__ x,      // [B, T, D]
    const float* __restrict__ w,      // [4, D]
    float* __restrict__ y)            // [B, T, D]
{
    unsigned idx = blockIdx.x * blockDim.x + threadIdx.x;
    // idx -> (b, tc, d8), d8 fastest for coalescing
    unsigned d8   = idx & (D8 - 1);
    unsigned rest = idx >> 8;             // / D8
    unsigned tc   = rest & (NCH - 1);
    unsigned b    = rest >> 9;            // / NCH

    size_t base = ((size_t)b * T_DIM + (size_t)tc * TC) * D_DIM + (size_t)d8 * 8;
    const float* __restrict__ xp = x + base;
    float*       __restrict__ yp = y + base;

    // per-channel weights (tiny; L2-resident)
    f8 w0 = ld8(w + 0 * D_DIM + d8 * 8);
    f8 w1 = ld8(w + 1 * D_DIM + d8 * 8);
    f8 w2 = ld8(w + 2 * D_DIM + d8 * 8);
    f8 w3 = ld8(w + 3 * D_DIM + d8 * 8);

    // history: x[t-3], x[t-2], x[t-1]
    f8 xm3, xm2, xm1;
    if (tc > 0) {
        xm3 = ld8(xp - 3 * D_DIM);
        xm2 = ld8(xp - 2 * D_DIM);
        xm1 = ld8(xp - 1 * D_DIM);
    } else {
#pragma unroll
        for (int j = 0; j < 8; ++j) { xm3.v[j] = 0.f; xm2.v[j] = 0.f; xm1.v[j] = 0.f; }
    }

#pragma unroll
    for (int i = 0; i < TC; ++i) {
        f8 cur = ld8(xp + i * D_DIM);

        f8 out;
#pragma unroll
        for (int j = 0; j < 8; ++j) {
            float acc = fmaf(w3.v[j], cur.v[j],
                        fmaf(w2.v[j], xm1.v[j],
                        fmaf(w1.v[j], xm2.v[j], w0.v[j] * xm3.v[j])));
            out.v[j] = silu_f(acc);
        }

        st8(yp + i * D_DIM, out);

        xm3 = xm2;
        xm2 = xm1;
        xm1 = cur;
    }
}

extern "C" void kernel_launch(void* const* d_in, const int* in_sizes, int n_in,
                              void* d_out, int out_size)
{
    const float* x = (const float*)d_in[0];   // (B, T, D) float32
    const float* w = (const float*)d_in[1];   // (W, 1, D) float32
    float* y = (float*)d_out;

    const unsigned total_threads = B_DIM * NCH * D8;   // 1,048,576
    const unsigned block = 256;
    const unsigned grid = total_threads / block;       // 4096

    conv_silu_kernel<<<grid, block>>>(x, w, y);
}

// round 8
// speedup vs baseline: 1.1997x; 1.1997x over previous
#include <cuda_runtime.h>

// B=8, T=4096, D=2048, W=4
// y[b,t,d] = silu( sum_{k=0..3} w[k,d] * x[b, t-3+k, d] )  (zero-pad t<0)
//
// Phase-separated streaming kernel (R3 config + explicit batching):
//  - float4, d-fastest, TC=8 sliding window per thread
//  - ALL 11 x-loads issued up front (MLP=11, read burst)
//  - compute 8 outputs into registers
//  - ALL 8 stores issued at the end (write burst, evict-first)

#define B_DIM 8
#define T_DIM 4096
#define D_DIM 2048
#define D4    (D_DIM / 4)       // 512 float4 per row
#define TC    8                 // t-values per thread
#define NCH   (T_DIM / TC)      // 512 chunks per batch

// silu(v) = 0.5*v*(1 + tanh(0.5*v))  -> single MUFU.TANH
__device__ __forceinline__ float silu_f(float v) {
    float t;
    asm("tanh.approx.f32 %0, %1;" : "=f"(t) : "f"(0.5f * v));
    return fmaf(0.5f * v, t, 0.5f * v);
}

__global__ __launch_bounds__(256) void conv_silu_kernel(
    const float4* __restrict__ x,     // [B, T, D4]
    const float4* __restrict__ w,     // [4, D4]
    float4* __restrict__ y)           // [B, T, D4]
{
    unsigned idx = blockIdx.x * blockDim.x + threadIdx.x;
    // idx -> (b, tc, d4), d4 fastest for coalescing
    unsigned d4   = idx & (D4 - 1);
    unsigned rest = idx >> 9;             // / D4
    unsigned tc   = rest & (NCH - 1);
    unsigned b    = rest >> 9;            // / NCH

    size_t base = ((size_t)b * T_DIM + (size_t)tc * TC) * D4 + d4;
    const float4* __restrict__ xp = x + base;
    float4*       __restrict__ yp = y + base;

    // ---- phase 1: read burst --------------------------------------------
    // xv[j] = x[t0 - 3 + j], j = 0..10  (t0 = tc*TC)
    float4 xv[TC + 3];
    if (tc > 0) {
#pragma unroll
        for (int j = 0; j < TC + 3; ++j)
            xv[j] = xp[(j - 3) * (int)D4];
    } else {
        xv[0] = make_float4(0.f, 0.f, 0.f, 0.f);
        xv[1] = xv[0];
        xv[2] = xv[0];
#pragma unroll
        for (int j = 3; j < TC + 3; ++j)
            xv[j] = xp[(j - 3) * (int)D4];
    }

    // weights (tiny; L2-resident)
    float4 w0 = w[0 * D4 + d4];
    float4 w1 = w[1 * D4 + d4];
    float4 w2 = w[2 * D4 + d4];
    float4 w3 = w[3 * D4 + d4];

    // ---- phase 2: compute ----------------------------------------------
    float4 out[TC];
#pragma unroll
    for (int i = 0; i < TC; ++i) {
        float4 a, bb, c, d;
        a  = xv[i];       // t-3
        bb = xv[i + 1];   // t-2
        c  = xv[i + 2];   // t-1
        d  = xv[i + 3];   // t

        float4 acc;
        acc.x = fmaf(w3.x, d.x, fmaf(w2.x, c.x, fmaf(w1.x, bb.x, w0.x * a.x)));
        acc.y = fmaf(w3.y, d.y, fmaf(w2.y, c.y, fmaf(w1.y, bb.y, w0.y * a.y)));
        acc.z = fmaf(w3.z, d.z, fmaf(w2.z, c.z, fmaf(w1.z, bb.z, w0.z * a.z)));
        acc.w = fmaf(w3.w, d.w, fmaf(w2.w, c.w, fmaf(w1.w, bb.w, w0.w * a.w)));

        out[i].x = silu_f(acc.x);
        out[i].y = silu_f(acc.y);
        out[i].z = silu_f(acc.z);
        out[i].w = silu_f(acc.w);
    }

    // ---- phase 3: write burst ------------------------------------------
#pragma unroll
    for (int i = 0; i < TC; ++i)
        __stcs(&yp[i * D4], out[i]);
}

extern "C" void kernel_launch(void* const* d_in, const int* in_sizes, int n_in,
                              void* d_out, int out_size)
{
    const float4* x = (const float4*)d_in[0];   // (B, T, D) float32
    const float4* w = (const float4*)d_in[1];   // (W, 1, D) float32
    float4* y = (float4*)d_out;

    const unsigned total_threads = B_DIM * NCH * D4;   // 2,097,152
    const unsigned block = 256;
    const unsigned grid = total_threads / block;       // 8192

    conv_silu_kernel<<<grid, block>>>(x, w, y);
}

// round 9
// speedup vs baseline: 1.2053x; 1.0047x over previous
#include <cuda_runtime.h>

// B=8, T=4096, D=2048, W=4
// y[b,t,d] = silu( sum_{k=0..3} w[k,d] * x[b, t-3+k, d] )  (zero-pad t<0)
//
// Converged HBM-roofline kernel (best of 8 measured variants):
//  - float4 loads/stores, d-fastest mapping (perfect 128B coalescing)
//  - per-thread sliding window over TC=8 timesteps (halo absorbed in L2)
//  - default-policy loads (compiler-scheduled LDG.128, max batching)
//  - evict-first streaming stores on y (never re-read)
//  - 1-MUFU silu via tanh.approx: silu(v) = 0.5*v*(1 + tanh(0.5*v))
// Measured: ~76us kernel, 6.3 TB/s bus = 7.07 TB/s effective unique-byte
// bandwidth (88% of spec) — at the mixed-R/W DRAM ceiling.

#define B_DIM 8
#define T_DIM 4096
#define D_DIM 2048
#define D4    (D_DIM / 4)       // 512 float4 per row
#define TC    8                 // t-values per thread (sliding window)
#define NCH   (T_DIM / TC)      // 512 chunks per batch

__device__ __forceinline__ float silu_f(float v) {
    float t;
    asm("tanh.approx.f32 %0, %1;" : "=f"(t) : "f"(0.5f * v));
    return fmaf(0.5f * v, t, 0.5f * v);
}

__global__ __launch_bounds__(256) void conv_silu_kernel(
    const float4* __restrict__ x,     // [B, T, D4]
    const float4* __restrict__ w,     // [4, D4]
    float4* __restrict__ y)           // [B, T, D4]
{
    unsigned idx = blockIdx.x * blockDim.x + threadIdx.x;
    // idx -> (b, tc, d4), d4 fastest for coalescing
    unsigned d4   = idx & (D4 - 1);
    unsigned rest = idx >> 9;             // / D4
    unsigned tc   = rest & (NCH - 1);
    unsigned b    = rest >> 9;            // / NCH

    size_t base = ((size_t)b * T_DIM + (size_t)tc * TC) * D4 + d4;
    const float4* __restrict__ xp = x + base;
    float4*       __restrict__ yp = y + base;

    // per-channel weights (32 KB total; L2-resident)
    float4 w0 = w[0 * D4 + d4];
    float4 w1 = w[1 * D4 + d4];
    float4 w2 = w[2 * D4 + d4];
    float4 w3 = w[3 * D4 + d4];

    // history: x[t-3], x[t-2], x[t-1]
    float4 xm3, xm2, xm1;
    if (tc > 0) {
        xm3 = xp[-3 * (int)D4];
        xm2 = xp[-2 * (int)D4];
        xm1 = xp[-1 * (int)D4];
    } else {
        xm3 = make_float4(0.f, 0.f, 0.f, 0.f);
        xm2 = xm3;
        xm1 = xm3;
    }

#pragma unroll
    for (int i = 0; i < TC; ++i) {
        float4 cur = xp[i * D4];

        float4 acc;
        acc.x = fmaf(w3.x, cur.x, fmaf(w2.x, xm1.x, fmaf(w1.x, xm2.x, w0.x * xm3.x)));
        acc.y = fmaf(w3.y, cur.y, fmaf(w2.y, xm1.y, fmaf(w1.y, xm2.y, w0.y * xm3.y)));
        acc.z = fmaf(w3.z, cur.z, fmaf(w2.z, xm1.z, fmaf(w1.z, xm2.z, w0.z * xm3.z)));
        acc.w = fmaf(w3.w, cur.w, fmaf(w2.w, xm1.w, fmaf(w1.w, xm2.w, w0.w * xm3.w)));

        float4 out;
        out.x = silu_f(acc.x);
        out.y = silu_f(acc.y);
        out.z = silu_f(acc.z);
        out.w = silu_f(acc.w);

        // streaming store: evict-first in L2 (output is never re-read)
        __stcs(&yp[i * D4], out);

        xm3 = xm2;
        xm2 = xm1;
        xm1 = cur;
    }
}

extern "C" void kernel_launch(void* const* d_in, const int* in_sizes, int n_in,
                              void* d_out, int out_size)
{
    const float4* x = (const float4*)d_in[0];   // (B, T, D) float32
    const float4* w = (const float4*)d_in[1];   // (W, 1, D) float32
    float4* y = (float4*)d_out;

    const unsigned total_threads = B_DIM * NCH * D4;   // 2,097,152
    const unsigned block = 256;
    const unsigned grid = total_threads / block;       // 8192

    conv_silu_kernel<<<grid, block>>>(x, w, y);
}

// round 10
// speedup vs baseline: 1.2058x; 1.0004x over previous
#include <cuda_runtime.h>

// B=8, T=4096, D=2048, W=4
// y[b,t,d] = silu( sum_{k=0..3} w[k,d] * x[b, t-3+k, d] )  (zero-pad t<0)
//
// HBM-roofline kernel, TC=4 variant: 4M threads, maximal warp-level MLP.
//  - float4 loads/stores, d-fastest mapping (perfect 128B coalescing)
//  - per-thread sliding window over TC=4 timesteps (halo absorbed in L2)
//  - default-policy loads (compiler-scheduled LDG.128, max batching)
//  - evict-first streaming stores on y (never re-read)
//  - 1-MUFU silu via tanh.approx: silu(v) = 0.5*v*(1 + tanh(0.5*v))

#define B_DIM 8
#define T_DIM 4096
#define D_DIM 2048
#define D4    (D_DIM / 4)       // 512 float4 per row
#define TC    4                 // t-values per thread (sliding window)
#define NCH   (T_DIM / TC)      // 1024 chunks per batch

__device__ __forceinline__ float silu_f(float v) {
    float t;
    asm("tanh.approx.f32 %0, %1;" : "=f"(t) : "f"(0.5f * v));
    return fmaf(0.5f * v, t, 0.5f * v);
}

__global__ __launch_bounds__(256) void conv_silu_kernel(
    const float4* __restrict__ x,     // [B, T, D4]
    const float4* __restrict__ w,     // [4, D4]
    float4* __restrict__ y)           // [B, T, D4]
{
    unsigned idx = blockIdx.x * blockDim.x + threadIdx.x;
    // idx -> (b, tc, d4), d4 fastest for coalescing
    unsigned d4   = idx & (D4 - 1);
    unsigned rest = idx >> 9;             // / D4
    unsigned tc   = rest & (NCH - 1);
    unsigned b    = rest >> 10;           // / NCH

    size_t base = ((size_t)b * T_DIM + (size_t)tc * TC) * D4 + d4;
    const float4* __restrict__ xp = x + base;
    float4*       __restrict__ yp = y + base;

    // per-channel weights (32 KB total; L2-resident)
    float4 w0 = w[0 * D4 + d4];
    float4 w1 = w[1 * D4 + d4];
    float4 w2 = w[2 * D4 + d4];
    float4 w3 = w[3 * D4 + d4];

    // history: x[t-3], x[t-2], x[t-1]
    float4 xm3, xm2, xm1;
    if (tc > 0) {
        xm3 = xp[-3 * (int)D4];
        xm2 = xp[-2 * (int)D4];
        xm1 = xp[-1 * (int)D4];
    } else {
        xm3 = make_float4(0.f, 0.f, 0.f, 0.f);
        xm2 = xm3;
        xm1 = xm3;
    }

#pragma unroll
    for (int i = 0; i < TC; ++i) {
        float4 cur = xp[i * D4];

        float4 acc;
        acc.x = fmaf(w3.x, cur.x, fmaf(w2.x, xm1.x, fmaf(w1.x, xm2.x, w0.x * xm3.x)));
        acc.y = fmaf(w3.y, cur.y, fmaf(w2.y, xm1.y, fmaf(w1.y, xm2.y, w0.y * xm3.y)));
        acc.z = fmaf(w3.z, cur.z, fmaf(w2.z, xm1.z, fmaf(w1.z, xm2.z, w0.z * xm3.z)));
        acc.w = fmaf(w3.w, cur.w, fmaf(w2.w, xm1.w, fmaf(w1.w, xm2.w, w0.w * xm3.w)));

        float4 out;
        out.x = silu_f(acc.x);
        out.y = silu_f(acc.y);
        out.z = silu_f(acc.z);
        out.w = silu_f(acc.w);

        // streaming store: evict-first in L2 (output is never re-read)
        __stcs(&yp[i * D4], out);

        xm3 = xm2;
        xm2 = xm1;
        xm1 = cur;
    }
}

extern "C" void kernel_launch(void* const* d_in, const int* in_sizes, int n_in,
                              void* d_out, int out_size)
{
    const float4* x = (const float4*)d_in[0];   // (B, T, D) float32
    const float4* w = (const float4*)d_in[1];   // (W, 1, D) float32
    float4* y = (float4*)d_out;

    const unsigned total_threads = B_DIM * NCH * D4;   // 4,194,304
    const unsigned block = 256;
    const unsigned grid = total_threads / block;       // 16384

    conv_silu_kernel<<<grid, block>>>(x, w, y);
}